// round 1
// baseline (speedup 1.0000x reference)
#include <cuda_runtime.h>
#include <cuda_bf16.h>
#include <cstdint>
#include <cfloat>

// Problem constants
#define BB 32
#define TT 2048
#define DD 1024
#define KK 31          // conv kernel width
#define PAD 15

// ---------------- device scratch (no allocations allowed) ----------------
__device__ float g_qproj[BB * DD];          // query @ Wq^T
__device__ float g_e[BB * TT];              // pre-softmax energies
__device__ float g_wlocT[2 * KK * DD];      // Wloc transposed to [ch][k][d]
__device__ float g_ctxp[4 * BB * DD];       // 4 t-segment partials of ctx
__device__ int   g_maskmode;                // 1 = 1-byte mask, 0 = 4-byte mask

__device__ __forceinline__ float fast_tanh(float x) {
    float y;
    asm("tanh.approx.f32 %0, %1;" : "=f"(y) : "f"(x));
    return y;
}

// ---------------- mask dtype detection ----------------
// If the mask buffer is 4-byte (int32 0/1 or float32 0.0/1.0), byte index %4==1
// is always zero. If it is 1-byte bool, ~16K of those positions are Bernoulli(0.2)
// -> some nonzero with probability 1-0.8^16384 ~ 1. Deterministic for fixed input.
__global__ void detect_mask_kernel(const unsigned char* __restrict__ m, int nbytes) {
    __shared__ int flag;
    if (threadIdx.x == 0) flag = 0;
    __syncthreads();
    int local = 0;
    for (int i = threadIdx.x; i < nbytes; i += blockDim.x) {
        if ((i & 3) == 1 && m[i] != 0) local = 1;
    }
    if (local) atomicOr(&flag, 1);
    __syncthreads();
    if (threadIdx.x == 0) g_maskmode = flag;
}

// ---------------- Wloc transpose: [d][ch][k] -> [ch][k][d] ----------------
__global__ void transpose_wloc_kernel(const float* __restrict__ Wloc) {
    int gt = blockIdx.x * blockDim.x + threadIdx.x;   // 0 .. 2*31*1024-1
    if (gt >= 2 * KK * DD) return;
    int d  = gt & (DD - 1);
    int k  = (gt >> 10) % KK;
    int ch = gt / (KK * DD);
    g_wlocT[gt] = Wloc[d * (2 * KK) + ch * KK + k];
}

// ---------------- qproj[b][e] = sum_d query[b][d] * Wq[e][d] ----------------
__global__ void qproj_kernel(const float* __restrict__ query,
                             const float* __restrict__ Wq) {
    __shared__ float qs[DD];
    int b = blockIdx.x;
    for (int i = threadIdx.x; i < DD; i += blockDim.x) qs[i] = query[b * DD + i];
    __syncthreads();
    int w = threadIdx.x >> 5, lane = threadIdx.x & 31;
    for (int e = w; e < DD; e += 8) {
        const float* wr = Wq + (size_t)e * DD;
        float acc = 0.f;
        #pragma unroll 4
        for (int k = lane; k < DD; k += 32) acc += qs[k] * wr[k];
        #pragma unroll
        for (int m = 16; m >= 1; m >>= 1) acc += __shfl_xor_sync(0xffffffffu, acc, m);
        if (lane == 0) g_qproj[b * DD + e] = acc;
    }
}

// ---------------- main fused kernel ----------------
// Computes e[b,t] = sum_d v[d] * tanh(qproj[b,d] + (memory[b,t,:]·Wm[d,:]) + loc[b,t,d])
// Tile: 128 rows (t) x full 1024 cols (d) in 8 chunks of 128; 8x8 per thread; BK=8.
__global__ void __launch_bounds__(256)
fused_e_kernel(const float* __restrict__ mem,
               const float* __restrict__ Wm,
               const float* __restrict__ prev,
               const float* __restrict__ cum,
               const float* __restrict__ vvec) {
    __shared__ float As[8][128];
    __shared__ float Bs[8][128];
    __shared__ float prev_s[128 + 2 * PAD];
    __shared__ float cum_s[128 + 2 * PAD];

    const int tid = threadIdx.x;
    const int tx = tid & 15;        // col group
    const int ty = tid >> 4;        // row group
    const int bidx = blockIdx.x;
    const int b  = bidx >> 4;               // 16 tiles per batch
    const int t0 = (bidx & 15) << 7;        // 128 rows per tile

    // conv windows (zero padded)
    for (int i = tid; i < 128 + 2 * PAD; i += 256) {
        int t = t0 - PAD + i;
        bool ok = (t >= 0) && (t < TT);
        prev_s[i] = ok ? prev[b * TT + t] : 0.f;
        cum_s[i]  = ok ? cum[b * TT + t]  : 0.f;
    }

    const int lrow = tid >> 1;      // 0..127
    const int lkp  = tid & 1;       // 0..1 -> k offset 0 or 4
    const float* Arow = mem + ((size_t)(b * TT + t0)) * DD;

    float epart[8];
    #pragma unroll
    for (int i = 0; i < 8; i++) epart[i] = 0.f;

    const int ro = ty * 8;

    for (int n0 = 0; n0 < DD; n0 += 128) {
        float acc[8][8];
        #pragma unroll
        for (int i = 0; i < 8; i++)
            #pragma unroll
            for (int j = 0; j < 8; j++) acc[i][j] = 0.f;

        for (int k0 = 0; k0 < DD; k0 += 8) {
            __syncthreads();
            float4 av = *(const float4*)(Arow + (size_t)lrow * DD + k0 + lkp * 4);
            float4 bv = *(const float4*)(Wm + (size_t)(n0 + lrow) * DD + k0 + lkp * 4);
            As[lkp * 4 + 0][lrow] = av.x;
            As[lkp * 4 + 1][lrow] = av.y;
            As[lkp * 4 + 2][lrow] = av.z;
            As[lkp * 4 + 3][lrow] = av.w;
            Bs[lkp * 4 + 0][lrow] = bv.x;
            Bs[lkp * 4 + 1][lrow] = bv.y;
            Bs[lkp * 4 + 2][lrow] = bv.z;
            Bs[lkp * 4 + 3][lrow] = bv.w;
            __syncthreads();

            #pragma unroll
            for (int kk = 0; kk < 8; kk++) {
                float af[8], bf[8];
                *(float4*)(af)     = *(const float4*)(&As[kk][ty * 8]);
                *(float4*)(af + 4) = *(const float4*)(&As[kk][ty * 8 + 4]);
                *(float4*)(bf)     = *(const float4*)(&Bs[kk][tx * 8]);
                *(float4*)(bf + 4) = *(const float4*)(&Bs[kk][tx * 8 + 4]);
                #pragma unroll
                for (int i = 0; i < 8; i++)
                    #pragma unroll
                    for (int j = 0; j < 8; j++)
                        acc[i][j] += af[i] * bf[j];
            }
        }

        // ---- epilogue: add location conv directly into acc ----
        const int dbase = n0 + tx * 8;
        const float* wl0 = g_wlocT + dbase;            // channel 0 (prev_attn)
        const float* wl1 = g_wlocT + KK * DD + dbase;  // channel 1 (cum_attn)
        #pragma unroll 1
        for (int k = 0; k < KK; k++) {
            float c0[8], c1[8];
            *(float4*)(c0)     = *(const float4*)(wl0 + k * DD);
            *(float4*)(c0 + 4) = *(const float4*)(wl0 + k * DD + 4);
            *(float4*)(c1)     = *(const float4*)(wl1 + k * DD);
            *(float4*)(c1 + 4) = *(const float4*)(wl1 + k * DD + 4);
            #pragma unroll
            for (int i = 0; i < 8; i++) {
                float pw = prev_s[ro + i + k];
                float cw = cum_s[ro + i + k];
                #pragma unroll
                for (int j = 0; j < 8; j++)
                    acc[i][j] += c0[j] * pw + c1[j] * cw;
            }
        }

        // ---- add qproj, tanh, dot with v ----
        float q8[8], v8[8];
        *(float4*)(q8)     = *(const float4*)(g_qproj + b * DD + dbase);
        *(float4*)(q8 + 4) = *(const float4*)(g_qproj + b * DD + dbase + 4);
        *(float4*)(v8)     = *(const float4*)(vvec + dbase);
        *(float4*)(v8 + 4) = *(const float4*)(vvec + dbase + 4);
        #pragma unroll
        for (int i = 0; i < 8; i++) {
            float s = 0.f;
            #pragma unroll
            for (int j = 0; j < 8; j++)
                s += v8[j] * fast_tanh(acc[i][j] + q8[j]);
            epart[i] += s;
        }
    }

    // reduce across the 16 tx lanes (lanes [0..15] / [16..31] hold distinct ty)
    #pragma unroll
    for (int i = 0; i < 8; i++) {
        float s = epart[i];
        s += __shfl_xor_sync(0xffffffffu, s, 8);
        s += __shfl_xor_sync(0xffffffffu, s, 4);
        s += __shfl_xor_sync(0xffffffffu, s, 2);
        s += __shfl_xor_sync(0xffffffffu, s, 1);
        if (tx == 0) g_e[b * TT + t0 + ro + i] = s;
    }
}

// ---------------- masked softmax over t ----------------
__global__ void softmax_kernel(const void* __restrict__ mask,
                               float* __restrict__ a_out) {
    __shared__ float red[256];
    const int b = blockIdx.x;
    const int tid = threadIdx.x;
    const int mode = g_maskmode;
    const unsigned char* m1 = (const unsigned char*)mask;
    const unsigned int*  m4 = (const unsigned int*)mask;

    float vals[8];
    float mx = -FLT_MAX;
    #pragma unroll
    for (int r = 0; r < 8; r++) {
        int i = tid + r * 256;
        int gi = b * TT + i;
        bool mk = mode ? (m1[gi] != 0) : (m4[gi] != 0);
        float vv = mk ? -FLT_MAX : g_e[gi];
        vals[r] = vv;
        mx = fmaxf(mx, vv);
    }
    red[tid] = mx; __syncthreads();
    for (int s = 128; s >= 1; s >>= 1) {
        if (tid < s) red[tid] = fmaxf(red[tid], red[tid + s]);
        __syncthreads();
    }
    mx = red[0]; __syncthreads();

    float sum = 0.f;
    #pragma unroll
    for (int r = 0; r < 8; r++) {
        float ex = expf(vals[r] - mx);   // -FLT_MAX -> 0
        vals[r] = ex;
        sum += ex;
    }
    red[tid] = sum; __syncthreads();
    for (int s = 128; s >= 1; s >>= 1) {
        if (tid < s) red[tid] += red[tid + s];
        __syncthreads();
    }
    float inv = 1.f / red[0];
    #pragma unroll
    for (int r = 0; r < 8; r++)
        a_out[b * TT + tid + r * 256] = vals[r] * inv;
}

// ---------------- ctx partial: per 512-t segment ----------------
__global__ void ctx_part_kernel(const float* __restrict__ mem,
                                const float* __restrict__ a) {
    __shared__ float a_s[512];
    const int b = blockIdx.y;
    const int seg = blockIdx.z;
    const int tid = threadIdx.x;
    for (int i = tid; i < 512; i += 256)
        a_s[i] = a[b * TT + seg * 512 + i];
    __syncthreads();
    const int d = blockIdx.x * 256 + tid;
    const float* mp = mem + ((size_t)(b * TT + seg * 512)) * DD + d;
    float acc = 0.f;
    #pragma unroll 8
    for (int t = 0; t < 512; t++)
        acc += a_s[t] * mp[(size_t)t * DD];
    g_ctxp[((seg * BB) + b) * DD + d] = acc;
}

__global__ void ctx_reduce_kernel(float* __restrict__ out_ctx) {
    int i = blockIdx.x * 256 + threadIdx.x;   // 0..32767
    out_ctx[i] = g_ctxp[i] + g_ctxp[BB * DD + i] +
                 g_ctxp[2 * BB * DD + i] + g_ctxp[3 * BB * DD + i];
}

// ---------------- launch ----------------
extern "C" void kernel_launch(void* const* d_in, const int* in_sizes, int n_in,
                              void* d_out, int out_size) {
    const float* query = (const float*)d_in[0];
    const float* mem   = (const float*)d_in[1];
    const float* prev  = (const float*)d_in[2];
    const float* cum   = (const float*)d_in[3];
    const void*  mask  = d_in[4];
    const float* Wq    = (const float*)d_in[5];
    const float* Wm    = (const float*)d_in[6];
    const float* Wloc  = (const float*)d_in[7];
    const float* v     = (const float*)d_in[8];

    float* out_ctx = (float*)d_out;             // [32,1024]
    float* out_a   = (float*)d_out + BB * DD;   // [32,2048]

    detect_mask_kernel<<<1, 256>>>((const unsigned char*)mask, in_sizes[4]);
    transpose_wloc_kernel<<<(2 * KK * DD + 255) / 256, 256>>>(Wloc);
    qproj_kernel<<<BB, 256>>>(query, Wq);
    fused_e_kernel<<<(BB * TT) / 128, 256>>>(mem, Wm, prev, cum, v);
    softmax_kernel<<<BB, 256>>>(mask, out_a);
    ctx_part_kernel<<<dim3(DD / 256, BB, 4), 256>>>(mem, out_a);
    ctx_reduce_kernel<<<(BB * DD) / 256, 256>>>(out_ctx);
}

// round 3
// speedup vs baseline: 3.5428x; 3.5428x over previous
#include <cuda_runtime.h>
#include <cstdint>
#include <cfloat>

#define BB 32
#define TT 2048
#define DD 1024
#define KEXT 1088          // 1024 + 62 conv taps + 2 zero pad
#define NSL 34             // 1088/32 K-slices
#define ASTRIDE 36         // padded floats per row (bank-conflict-free fragments)
#define STG_FLOATS (128 * ASTRIDE)          // per operand tile
#define STG_BYTES  (2 * STG_FLOATS * 4)     // A + B = 36864 B
// dynamic smem layout
#define QOFF   (3 * STG_BYTES)              // 110592
#define VOFF   (QOFF + 512)
#define PWOFF  (VOFF + 512)
#define CWOFF  (PWOFF + 640)
#define EROFF  (CWOFF + 640)
#define SMEM_TOTAL (EROFF + 512)            // 113408

// ---------------- device scratch ----------------
__device__ float g_qproj[BB * DD];
__device__ float g_e[BB * TT];
__device__ float g_WmExt[DD * KEXT];        // [d][kext], tf32-rounded
__device__ float g_ctxp[4 * BB * DD];
__device__ int   g_maskmode;

__device__ __forceinline__ float fast_tanh(float x) {
    float y; asm("tanh.approx.f32 %0, %1;" : "=f"(y) : "f"(x)); return y;
}
__device__ __forceinline__ void cp16(void* dst, const void* src) {
    uint32_t d;
    asm("{ .reg .u64 t; cvta.to.shared.u64 t, %1; cvt.u32.u64 %0, t; }" : "=r"(d) : "l"(dst));
    asm volatile("cp.async.cg.shared.global [%0], [%1], 16;" :: "r"(d), "l"(src));
}
__device__ __forceinline__ void mma8(float* c, uint32_t a0, uint32_t a1,
                                     uint32_t a2, uint32_t a3,
                                     uint32_t b0, uint32_t b1) {
    asm volatile(
        "mma.sync.aligned.m16n8k8.row.col.f32.tf32.tf32.f32 "
        "{%0,%1,%2,%3}, {%4,%5,%6,%7}, {%8,%9}, {%0,%1,%2,%3};"
        : "+f"(c[0]), "+f"(c[1]), "+f"(c[2]), "+f"(c[3])
        : "r"(a0), "r"(a1), "r"(a2), "r"(a3), "r"(b0), "r"(b1));
}

// ---------------- mask dtype detection (deterministic) ----------------
__global__ void detect_mask_kernel(const unsigned char* __restrict__ m, int nbytes) {
    __shared__ int flag;
    if (threadIdx.x == 0) flag = 0;
    __syncthreads();
    int local = 0;
    for (int i = threadIdx.x; i < nbytes; i += blockDim.x)
        if ((i & 3) == 1 && m[i] != 0) local = 1;
    if (local) atomicOr(&flag, 1);
    __syncthreads();
    if (threadIdx.x == 0) g_maskmode = flag;
}

// ---------------- B-ext = [Wm | Wloc | 0], tf32 rounded ----------------
__global__ void prep_wmext_kernel(const float* __restrict__ Wm,
                                  const float* __restrict__ Wloc) {
    int idx = blockIdx.x * 256 + threadIdx.x;
    if (idx >= DD * KEXT) return;
    int d = idx / KEXT, k = idx - d * KEXT;
    float v = 0.f;
    if (k < 1024)      v = Wm[d * 1024 + k];
    else if (k < 1086) v = Wloc[d * 62 + (k - 1024)];   // [d][ch][tap] contiguous
    uint32_t bits;
    asm("cvt.rna.tf32.f32 %0, %1;" : "=r"(bits) : "f"(v));
    g_WmExt[idx] = __uint_as_float(bits);
}

__global__ void zero_e_kernel() { g_e[blockIdx.x * 256 + threadIdx.x] = 0.f; }

// ---------------- qproj ----------------
__global__ void __launch_bounds__(256) qproj_kernel(const float* __restrict__ query,
                                                    const float* __restrict__ Wq) {
    __shared__ float qs[DD];
    int b = blockIdx.x >> 3, ec = blockIdx.x & 7;
    int tid = threadIdx.x;
    for (int i = tid; i < DD; i += 256) qs[i] = query[b * DD + i];
    __syncthreads();
    int w = tid >> 5, lane = tid & 31;
    for (int i = 0; i < 16; i++) {
        int e = ec * 128 + w * 16 + i;
        const float* wr = Wq + (size_t)e * DD;
        float acc = 0.f;
        #pragma unroll 8
        for (int k = lane; k < DD; k += 32) acc += qs[k] * wr[k];
        #pragma unroll
        for (int m = 16; m >= 1; m >>= 1) acc += __shfl_xor_sync(0xffffffffu, acc, m);
        if (lane == 0) g_qproj[b * DD + e] = acc;
    }
}

// ---------------- main: TF32 mma.sync GEMM with folded conv ----------------
// grid 4096: nch = bx&7 (128 d's), mt = bx>>3; b = mt>>4, t0 = (mt&15)*128
__global__ void __launch_bounds__(256, 1)
fused_mma_kernel(const float* __restrict__ mem,
                 const float* __restrict__ prev,
                 const float* __restrict__ cum,
                 const float* __restrict__ vvec) {
    extern __shared__ char smem[];
    const int tid = threadIdx.x;
    const int bx = blockIdx.x;
    const int nch = bx & 7;
    const int mt  = bx >> 3;
    const int b   = mt >> 4;
    const int t0  = (mt & 15) << 7;
    const int d0  = nch << 7;

    float* q_s   = (float*)(smem + QOFF);
    float* v_s   = (float*)(smem + VOFF);
    float* pwin  = (float*)(smem + PWOFF);
    float* cwin  = (float*)(smem + CWOFF);
    float* e_red = (float*)(smem + EROFF);

    if (tid < 128) {
        q_s[tid] = g_qproj[b * DD + d0 + tid];
        v_s[tid] = vvec[d0 + tid];
        e_red[tid] = 0.f;
    }
    for (int i = tid; i < 158; i += 256) {
        int t = t0 - 15 + i;
        bool ok = (unsigned)t < TT;
        pwin[i] = ok ? prev[b * TT + t] : 0.f;
        cwin[i] = ok ? cum[b * TT + t] : 0.f;
    }
    __syncthreads();

    const size_t arow0 = ((size_t)(b * TT + t0)) * DD;

    auto issue_loads = [&](int s) {
        char* stg = smem + (s % 3) * STG_BYTES;
        float* Af = (float*)stg;
        if (s < 32) {
            #pragma unroll
            for (int it = 0; it < 4; it++) {
                int i = tid + it * 256;
                int row = i >> 3, c = i & 7;
                cp16(Af + row * ASTRIDE + c * 4,
                     mem + arow0 + (size_t)row * DD + s * 32 + c * 4);
            }
        } else {
            int j0 = (s - 32) * 32;
            #pragma unroll
            for (int it = 0; it < 16; it++) {
                int i = tid + it * 256;
                int row = i >> 5, col = i & 31;
                int je = j0 + col;
                float val = 0.f;
                if (je < 31)      val = pwin[row + je];
                else if (je < 62) val = cwin[row + je - 31];
                Af[row * ASTRIDE + col] = val;
            }
        }
        float* Bf = (float*)(stg + STG_FLOATS * 4);
        #pragma unroll
        for (int it = 0; it < 4; it++) {
            int i = tid + it * 256;
            int row = i >> 3, c = i & 7;
            cp16(Bf + row * ASTRIDE + c * 4,
                 g_WmExt + (size_t)(d0 + row) * KEXT + s * 32 + c * 4);
        }
        asm volatile("cp.async.commit_group;" ::: "memory");
    };

    issue_loads(0); issue_loads(1); issue_loads(2);

    const int warp = tid >> 5, lane = tid & 31;
    const int wm = warp & 1;          // 2 warps in M (64 rows each)
    const int wn = warp >> 1;         // 4 warps in N (32 cols each)
    const int gid = lane >> 2, tig = lane & 3;

    float acc[4][4][4];
    #pragma unroll
    for (int i = 0; i < 4; i++)
        #pragma unroll
        for (int j = 0; j < 4; j++)
            #pragma unroll
            for (int r = 0; r < 4; r++) acc[i][j][r] = 0.f;

    for (int s = 0; s < NSL; s++) {
        if (s < 32)       asm volatile("cp.async.wait_group 2;" ::: "memory");
        else if (s == 32) asm volatile("cp.async.wait_group 1;" ::: "memory");
        else              asm volatile("cp.async.wait_group 0;" ::: "memory");
        __syncthreads();

        const float* Af = (const float*)(smem + (s % 3) * STG_BYTES);
        const float* Bf = Af + STG_FLOATS;

        #pragma unroll
        for (int ks = 0; ks < 4; ks++) {
            const int kk0 = ks * 8;
            uint32_t afr[4][4], bfr[4][2];
            #pragma unroll
            for (int i = 0; i < 4; i++) {
                int rb = wm * 64 + i * 16;
                afr[i][0] = __float_as_uint(Af[(rb + gid) * ASTRIDE + kk0 + tig]);
                afr[i][1] = __float_as_uint(Af[(rb + gid + 8) * ASTRIDE + kk0 + tig]);
                afr[i][2] = __float_as_uint(Af[(rb + gid) * ASTRIDE + kk0 + tig + 4]);
                afr[i][3] = __float_as_uint(Af[(rb + gid + 8) * ASTRIDE + kk0 + tig + 4]);
            }
            #pragma unroll
            for (int j = 0; j < 4; j++) {
                int cb = wn * 32 + j * 8;
                bfr[j][0] = __float_as_uint(Bf[(cb + gid) * ASTRIDE + kk0 + tig]);
                bfr[j][1] = __float_as_uint(Bf[(cb + gid) * ASTRIDE + kk0 + tig + 4]);
            }
            #pragma unroll
            for (int i = 0; i < 4; i++)
                #pragma unroll
                for (int j = 0; j < 4; j++)
                    mma8(acc[i][j], afr[i][0], afr[i][1], afr[i][2], afr[i][3],
                         bfr[j][0], bfr[j][1]);
        }
        __syncthreads();
        if (s + 3 < NSL) issue_loads(s + 3);
    }

    // ---- epilogue: e_row += sum_d v[d] * tanh(acc + qproj) ----
    #pragma unroll
    for (int i = 0; i < 4; i++) {
        int r0 = wm * 64 + i * 16 + gid;
        float s0 = 0.f, s1 = 0.f;
        #pragma unroll
        for (int j = 0; j < 4; j++) {
            int cb = wn * 32 + j * 8 + 2 * tig;
            float q0 = q_s[cb], q1 = q_s[cb + 1];
            float v0 = v_s[cb], v1 = v_s[cb + 1];
            s0 += v0 * fast_tanh(acc[i][j][0] + q0) + v1 * fast_tanh(acc[i][j][1] + q1);
            s1 += v0 * fast_tanh(acc[i][j][2] + q0) + v1 * fast_tanh(acc[i][j][3] + q1);
        }
        s0 += __shfl_xor_sync(0xffffffffu, s0, 1);
        s0 += __shfl_xor_sync(0xffffffffu, s0, 2);
        s1 += __shfl_xor_sync(0xffffffffu, s1, 1);
        s1 += __shfl_xor_sync(0xffffffffu, s1, 2);
        if (tig == 0) {
            atomicAdd(&e_red[r0], s0);
            atomicAdd(&e_red[r0 + 8], s1);
        }
    }
    __syncthreads();
    if (tid < 128) atomicAdd(&g_e[b * TT + t0 + tid], e_red[tid]);
}

// ---------------- masked softmax ----------------
__global__ void softmax_kernel(const void* __restrict__ mask,
                               float* __restrict__ a_out) {
    __shared__ float red[256];
    const int b = blockIdx.x, tid = threadIdx.x;
    const int mode = g_maskmode;
    const unsigned char* m1 = (const unsigned char*)mask;
    const unsigned int*  m4 = (const unsigned int*)mask;

    float vals[8];
    float mx = -FLT_MAX;
    #pragma unroll
    for (int r = 0; r < 8; r++) {
        int gi = b * TT + tid + r * 256;
        bool mk = mode ? (m1[gi] != 0) : (m4[gi] != 0);
        float vv = mk ? -FLT_MAX : g_e[gi];
        vals[r] = vv;
        mx = fmaxf(mx, vv);
    }
    red[tid] = mx; __syncthreads();
    for (int s = 128; s >= 1; s >>= 1) {
        if (tid < s) red[tid] = fmaxf(red[tid], red[tid + s]);
        __syncthreads();
    }
    mx = red[0]; __syncthreads();

    float sum = 0.f;
    #pragma unroll
    for (int r = 0; r < 8; r++) {
        float ex = expf(vals[r] - mx);
        vals[r] = ex;
        sum += ex;
    }
    red[tid] = sum; __syncthreads();
    for (int s = 128; s >= 1; s >>= 1) {
        if (tid < s) red[tid] += red[tid + s];
        __syncthreads();
    }
    float inv = 1.f / red[0];
    #pragma unroll
    for (int r = 0; r < 8; r++)
        a_out[b * TT + tid + r * 256] = vals[r] * inv;
}

// ---------------- ctx GEMV ----------------
__global__ void ctx_part_kernel(const float* __restrict__ mem,
                                const float* __restrict__ a) {
    __shared__ float a_s[512];
    const int b = blockIdx.y, seg = blockIdx.z, tid = threadIdx.x;
    for (int i = tid; i < 512; i += 256)
        a_s[i] = a[b * TT + seg * 512 + i];
    __syncthreads();
    const int d = blockIdx.x * 256 + tid;
    const float* mp = mem + ((size_t)(b * TT + seg * 512)) * DD + d;
    float acc = 0.f;
    #pragma unroll 8
    for (int t = 0; t < 512; t++)
        acc += a_s[t] * mp[(size_t)t * DD];
    g_ctxp[((seg * BB) + b) * DD + d] = acc;
}

__global__ void ctx_reduce_kernel(float* __restrict__ out_ctx) {
    int i = blockIdx.x * 256 + threadIdx.x;
    out_ctx[i] = g_ctxp[i] + g_ctxp[BB * DD + i] +
                 g_ctxp[2 * BB * DD + i] + g_ctxp[3 * BB * DD + i];
}

// ---------------- launch ----------------
extern "C" void kernel_launch(void* const* d_in, const int* in_sizes, int n_in,
                              void* d_out, int out_size) {
    const float* query = (const float*)d_in[0];
    const float* mem   = (const float*)d_in[1];
    const float* prev  = (const float*)d_in[2];
    const float* cum   = (const float*)d_in[3];
    const void*  mask  = d_in[4];
    const float* Wq    = (const float*)d_in[5];
    const float* Wm    = (const float*)d_in[6];
    const float* Wloc  = (const float*)d_in[7];
    const float* v     = (const float*)d_in[8];

    float* out_ctx = (float*)d_out;
    float* out_a   = (float*)d_out + BB * DD;

    cudaFuncSetAttribute(fused_mma_kernel,
                         cudaFuncAttributeMaxDynamicSharedMemorySize, SMEM_TOTAL);

    detect_mask_kernel<<<1, 256>>>((const unsigned char*)mask, in_sizes[4]);
    prep_wmext_kernel<<<(DD * KEXT + 255) / 256, 256>>>(Wm, Wloc);
    qproj_kernel<<<256, 256>>>(query, Wq);
    zero_e_kernel<<<BB * TT / 256, 256>>>();
    fused_mma_kernel<<<4096, 256, SMEM_TOTAL>>>(mem, prev, cum, v);
    softmax_kernel<<<BB, 256>>>(mask, out_a);
    ctx_part_kernel<<<dim3(DD / 256, BB, 4), 256>>>(mem, out_a);
    ctx_reduce_kernel<<<(BB * DD) / 256, 256>>>(out_ctx);
}

// round 4
// speedup vs baseline: 5.6507x; 1.5950x over previous
#include <cuda_runtime.h>
#include <cuda_fp16.h>
#include <cstdint>
#include <cfloat>

#define BB 32
#define TT 2048
#define DD 1024
#define KEXT 1088            // 1024 + 62 conv taps + 2 zero pad
#define NSL 34               // 1088/32 K-slices
#define ROWH 40              // fp16 per smem row (conflict-free: 20 words, 20g%32 all distinct)
#define OPBYTES (128 * ROWH * 2)      // 10240 B per operand tile
#define STG_BYTES (2 * OPBYTES)       // 20480
#define QOFF   (3 * STG_BYTES)        // 61440
#define VOFF   (QOFF + 512)
#define PWOFF  (VOFF + 512)
#define CWOFF  (PWOFF + 640)
#define EROFF  (CWOFF + 640)
#define SMEM_TOTAL (EROFF + 512)      // 64256

// ---------------- device scratch ----------------
__device__ __half g_memh[BB * TT * DD];       // fp16 copy of memory
__device__ __half g_WmExth[DD * KEXT];        // fp16 [Wm | Wloc | 0]
__device__ float  g_qproj[BB * DD];
__device__ float  g_e[BB * TT];
__device__ float  g_ctxp[4 * BB * DD];
__device__ int    g_maskmode;

__device__ __forceinline__ float fast_tanh(float x) {
    float y; asm("tanh.approx.f32 %0, %1;" : "=f"(y) : "f"(x)); return y;
}
__device__ __forceinline__ void cp16(void* dst, const void* src) {
    uint32_t d;
    asm("{ .reg .u64 t; cvta.to.shared.u64 t, %1; cvt.u32.u64 %0, t; }" : "=r"(d) : "l"(dst));
    asm volatile("cp.async.cg.shared.global [%0], [%1], 16;" :: "r"(d), "l"(src));
}
__device__ __forceinline__ void mma16(float* c, uint32_t a0, uint32_t a1,
                                      uint32_t a2, uint32_t a3,
                                      uint32_t b0, uint32_t b1) {
    asm volatile(
        "mma.sync.aligned.m16n8k16.row.col.f32.f16.f16.f32 "
        "{%0,%1,%2,%3}, {%4,%5,%6,%7}, {%8,%9}, {%0,%1,%2,%3};"
        : "+f"(c[0]), "+f"(c[1]), "+f"(c[2]), "+f"(c[3])
        : "r"(a0), "r"(a1), "r"(a2), "r"(a3), "r"(b0), "r"(b1));
}

// ---------------- mask dtype detection (deterministic) ----------------
__global__ void detect_mask_kernel(const unsigned char* __restrict__ m, int nbytes) {
    __shared__ int flag;
    if (threadIdx.x == 0) flag = 0;
    __syncthreads();
    int local = 0;
    for (int i = threadIdx.x; i < nbytes; i += blockDim.x)
        if ((i & 3) == 1 && m[i] != 0) local = 1;
    if (local) atomicOr(&flag, 1);
    __syncthreads();
    if (threadIdx.x == 0) g_maskmode = flag;
}

// ---------------- memory fp32 -> fp16 ----------------
__global__ void __launch_bounds__(256) prep_memh_kernel(const float* __restrict__ mem) {
    int idx = blockIdx.x * 256 + threadIdx.x;       // over float4s
    float4 v = ((const float4*)mem)[idx];
    __half2 h0 = __floats2half2_rn(v.x, v.y);
    __half2 h1 = __floats2half2_rn(v.z, v.w);
    uint2 pack = make_uint2(*(uint32_t*)&h0, *(uint32_t*)&h1);
    ((uint2*)g_memh)[idx] = pack;
}

// ---------------- B-ext = [Wm | Wloc | 0] fp16 ----------------
__global__ void prep_wmext_kernel(const float* __restrict__ Wm,
                                  const float* __restrict__ Wloc) {
    int idx = blockIdx.x * 256 + threadIdx.x;
    if (idx >= DD * KEXT) return;
    int d = idx / KEXT, k = idx - d * KEXT;
    float v = 0.f;
    if (k < 1024)      v = Wm[d * 1024 + k];
    else if (k < 1086) v = Wloc[d * 62 + (k - 1024)];   // [d][ch][tap] contiguous
    g_WmExth[idx] = __float2half_rn(v);
}

__global__ void zero_e_kernel() { g_e[blockIdx.x * 256 + threadIdx.x] = 0.f; }

// ---------------- qproj ----------------
__global__ void __launch_bounds__(256) qproj_kernel(const float* __restrict__ query,
                                                    const float* __restrict__ Wq) {
    __shared__ float qs[DD];
    int b = blockIdx.x >> 3, ec = blockIdx.x & 7;
    int tid = threadIdx.x;
    for (int i = tid; i < DD; i += 256) qs[i] = query[b * DD + i];
    __syncthreads();
    int w = tid >> 5, lane = tid & 31;
    for (int i = 0; i < 16; i++) {
        int e = ec * 128 + w * 16 + i;
        const float* wr = Wq + (size_t)e * DD;
        float acc = 0.f;
        #pragma unroll 8
        for (int k = lane; k < DD; k += 32) acc += qs[k] * wr[k];
        #pragma unroll
        for (int m = 16; m >= 1; m >>= 1) acc += __shfl_xor_sync(0xffffffffu, acc, m);
        if (lane == 0) g_qproj[b * DD + e] = acc;
    }
}

// ---------------- main: fp16 m16n8k16 GEMM with folded conv ----------------
__global__ void __launch_bounds__(256, 2)
fused_mma_kernel(const float* __restrict__ prev,
                 const float* __restrict__ cum,
                 const float* __restrict__ vvec) {
    extern __shared__ char smem[];
    const int tid = threadIdx.x;
    const int bx = blockIdx.x;
    const int nch = bx & 7;
    const int mt  = bx >> 3;
    const int b   = mt >> 4;
    const int t0  = (mt & 15) << 7;
    const int d0  = nch << 7;

    float* q_s   = (float*)(smem + QOFF);
    float* v_s   = (float*)(smem + VOFF);
    float* pwin  = (float*)(smem + PWOFF);
    float* cwin  = (float*)(smem + CWOFF);
    float* e_red = (float*)(smem + EROFF);

    if (tid < 128) {
        q_s[tid] = g_qproj[b * DD + d0 + tid];
        v_s[tid] = vvec[d0 + tid];
        e_red[tid] = 0.f;
    }
    for (int i = tid; i < 158; i += 256) {
        int t = t0 - 15 + i;
        bool ok = (unsigned)t < TT;
        pwin[i] = ok ? prev[b * TT + t] : 0.f;
        cwin[i] = ok ? cum[b * TT + t] : 0.f;
    }
    __syncthreads();

    const size_t arow0 = ((size_t)(b * TT + t0)) * DD;

    auto issue_loads = [&](int s) {
        char* stg = smem + (s % 3) * STG_BYTES;
        __half* Ah = (__half*)stg;
        if (s < 32) {
            #pragma unroll
            for (int it = 0; it < 2; it++) {
                int i = tid + it * 256;
                int row = i >> 2, c = i & 3;
                cp16(Ah + row * ROWH + c * 8,
                     g_memh + arow0 + (size_t)row * DD + s * 32 + c * 8);
            }
        } else {
            int j0 = (s - 32) * 32;
            #pragma unroll
            for (int it = 0; it < 16; it++) {
                int i = tid + it * 256;
                int row = i >> 5, col = i & 31;
                int je = j0 + col;
                float val = 0.f;
                if (je < 31)      val = pwin[row + je];
                else if (je < 62) val = cwin[row + je - 31];
                Ah[row * ROWH + col] = __float2half_rn(val);
            }
        }
        __half* Bh = (__half*)(stg + OPBYTES);
        #pragma unroll
        for (int it = 0; it < 2; it++) {
            int i = tid + it * 256;
            int row = i >> 2, c = i & 3;
            cp16(Bh + row * ROWH + c * 8,
                 g_WmExth + (size_t)(d0 + row) * KEXT + s * 32 + c * 8);
        }
        asm volatile("cp.async.commit_group;" ::: "memory");
    };

    issue_loads(0); issue_loads(1); issue_loads(2);

    const int warp = tid >> 5, lane = tid & 31;
    const int wm = warp & 1;          // 2 warps in M (64 rows)
    const int wn = warp >> 1;         // 4 warps in N (32 cols)
    const int gid = lane >> 2, tig = lane & 3;

    float acc[4][4][4];
    #pragma unroll
    for (int i = 0; i < 4; i++)
        #pragma unroll
        for (int j = 0; j < 4; j++)
            #pragma unroll
            for (int r = 0; r < 4; r++) acc[i][j][r] = 0.f;

    for (int s = 0; s < NSL; s++) {
        if (s < 32)       asm volatile("cp.async.wait_group 2;" ::: "memory");
        else if (s == 32) asm volatile("cp.async.wait_group 1;" ::: "memory");
        else              asm volatile("cp.async.wait_group 0;" ::: "memory");
        __syncthreads();

        const uint32_t* Aw = (const uint32_t*)(smem + (s % 3) * STG_BYTES);
        const uint32_t* Bw = (const uint32_t*)(smem + (s % 3) * STG_BYTES + OPBYTES);

        #pragma unroll
        for (int ks = 0; ks < 2; ks++) {
            const int kw = ks * 8 + tig;          // word (fp16x2) index within row
            uint32_t afr[4][4], bfr[4][2];
            #pragma unroll
            for (int i = 0; i < 4; i++) {
                int rb = wm * 64 + i * 16;
                afr[i][0] = Aw[(rb + gid) * 20 + kw];
                afr[i][1] = Aw[(rb + gid + 8) * 20 + kw];
                afr[i][2] = Aw[(rb + gid) * 20 + kw + 4];
                afr[i][3] = Aw[(rb + gid + 8) * 20 + kw + 4];
            }
            #pragma unroll
            for (int j = 0; j < 4; j++) {
                int cb = wn * 32 + j * 8;
                bfr[j][0] = Bw[(cb + gid) * 20 + kw];
                bfr[j][1] = Bw[(cb + gid) * 20 + kw + 4];
            }
            #pragma unroll
            for (int i = 0; i < 4; i++)
                #pragma unroll
                for (int j = 0; j < 4; j++)
                    mma16(acc[i][j], afr[i][0], afr[i][1], afr[i][2], afr[i][3],
                          bfr[j][0], bfr[j][1]);
        }
        __syncthreads();
        if (s + 3 < NSL) issue_loads(s + 3);
    }

    // ---- epilogue: e_row += sum_d v[d] * tanh(acc + qproj) ----
    #pragma unroll
    for (int i = 0; i < 4; i++) {
        int r0 = wm * 64 + i * 16 + gid;
        float s0 = 0.f, s1 = 0.f;
        #pragma unroll
        for (int j = 0; j < 4; j++) {
            int cb = wn * 32 + j * 8 + 2 * tig;
            float q0 = q_s[cb], q1 = q_s[cb + 1];
            float v0 = v_s[cb], v1 = v_s[cb + 1];
            s0 += v0 * fast_tanh(acc[i][j][0] + q0) + v1 * fast_tanh(acc[i][j][1] + q1);
            s1 += v0 * fast_tanh(acc[i][j][2] + q0) + v1 * fast_tanh(acc[i][j][3] + q1);
        }
        s0 += __shfl_xor_sync(0xffffffffu, s0, 1);
        s0 += __shfl_xor_sync(0xffffffffu, s0, 2);
        s1 += __shfl_xor_sync(0xffffffffu, s1, 1);
        s1 += __shfl_xor_sync(0xffffffffu, s1, 2);
        if (tig == 0) {
            atomicAdd(&e_red[r0], s0);
            atomicAdd(&e_red[r0 + 8], s1);
        }
    }
    __syncthreads();
    if (tid < 128) atomicAdd(&g_e[b * TT + t0 + tid], e_red[tid]);
}

// ---------------- masked softmax ----------------
__global__ void softmax_kernel(const void* __restrict__ mask,
                               float* __restrict__ a_out) {
    __shared__ float red[256];
    const int b = blockIdx.x, tid = threadIdx.x;
    const int mode = g_maskmode;
    const unsigned char* m1 = (const unsigned char*)mask;
    const unsigned int*  m4 = (const unsigned int*)mask;

    float vals[8];
    float mx = -FLT_MAX;
    #pragma unroll
    for (int r = 0; r < 8; r++) {
        int gi = b * TT + tid + r * 256;
        bool mk = mode ? (m1[gi] != 0) : (m4[gi] != 0);
        float vv = mk ? -FLT_MAX : g_e[gi];
        vals[r] = vv;
        mx = fmaxf(mx, vv);
    }
    red[tid] = mx; __syncthreads();
    for (int s = 128; s >= 1; s >>= 1) {
        if (tid < s) red[tid] = fmaxf(red[tid], red[tid + s]);
        __syncthreads();
    }
    mx = red[0]; __syncthreads();

    float sum = 0.f;
    #pragma unroll
    for (int r = 0; r < 8; r++) {
        float ex = expf(vals[r] - mx);
        vals[r] = ex;
        sum += ex;
    }
    red[tid] = sum; __syncthreads();
    for (int s = 128; s >= 1; s >>= 1) {
        if (tid < s) red[tid] += red[tid + s];
        __syncthreads();
    }
    float inv = 1.f / red[0];
    #pragma unroll
    for (int r = 0; r < 8; r++)
        a_out[b * TT + tid + r * 256] = vals[r] * inv;
}

// ---------------- ctx GEMV ----------------
__global__ void ctx_part_kernel(const float* __restrict__ mem,
                                const float* __restrict__ a) {
    __shared__ float a_s[512];
    const int b = blockIdx.y, seg = blockIdx.z, tid = threadIdx.x;
    for (int i = tid; i < 512; i += 256)
        a_s[i] = a[b * TT + seg * 512 + i];
    __syncthreads();
    const int d = blockIdx.x * 256 + tid;
    const float* mp = mem + ((size_t)(b * TT + seg * 512)) * DD + d;
    float acc = 0.f;
    #pragma unroll 8
    for (int t = 0; t < 512; t++)
        acc += a_s[t] * mp[(size_t)t * DD];
    g_ctxp[((seg * BB) + b) * DD + d] = acc;
}

__global__ void ctx_reduce_kernel(float* __restrict__ out_ctx) {
    int i = blockIdx.x * 256 + threadIdx.x;
    out_ctx[i] = g_ctxp[i] + g_ctxp[BB * DD + i] +
                 g_ctxp[2 * BB * DD + i] + g_ctxp[3 * BB * DD + i];
}

// ---------------- launch ----------------
extern "C" void kernel_launch(void* const* d_in, const int* in_sizes, int n_in,
                              void* d_out, int out_size) {
    const float* query = (const float*)d_in[0];
    const float* mem   = (const float*)d_in[1];
    const float* prev  = (const float*)d_in[2];
    const float* cum   = (const float*)d_in[3];
    const void*  mask  = d_in[4];
    const float* Wq    = (const float*)d_in[5];
    const float* Wm    = (const float*)d_in[6];
    const float* Wloc  = (const float*)d_in[7];
    const float* v     = (const float*)d_in[8];

    float* out_ctx = (float*)d_out;
    float* out_a   = (float*)d_out + BB * DD;

    cudaFuncSetAttribute(fused_mma_kernel,
                         cudaFuncAttributeMaxDynamicSharedMemorySize, SMEM_TOTAL);

    detect_mask_kernel<<<1, 256>>>((const unsigned char*)mask, in_sizes[4]);
    prep_memh_kernel<<<BB * TT * DD / 1024, 256>>>(mem);
    prep_wmext_kernel<<<(DD * KEXT + 255) / 256, 256>>>(Wm, Wloc);
    qproj_kernel<<<256, 256>>>(query, Wq);
    zero_e_kernel<<<BB * TT / 256, 256>>>();
    fused_mma_kernel<<<4096, 256, SMEM_TOTAL>>>(prev, cum, v);   // launch #5 -> ncu -s 5
    softmax_kernel<<<BB, 256>>>(mask, out_a);
    ctx_part_kernel<<<dim3(DD / 256, BB, 4), 256>>>(mem, out_a);
    ctx_reduce_kernel<<<(BB * DD) / 256, 256>>>(out_ctx);
}